// round 3
// baseline (speedup 1.0000x reference)
#include <cuda_runtime.h>

#define FEAT_D 128
#define MAX_NODES 50000

// Scratch (allocation-free rule: __device__ globals)
__device__ float    g_h[MAX_NODES * FEAT_D];       // pooled features after GEMM1
__device__ unsigned g_neigh[MAX_NODES * FEAT_D];   // order-encoded running max
__device__ int      g_idx64;                       // 1 if src/dst are int64, 0 if int32

// ---- order-preserving float <-> uint encoding for atomicMax ----
// All finite floats encode to values > 0u, so 0u is a safe "no edge" sentinel.
__device__ __forceinline__ unsigned fenc(float f) {
    unsigned u = __float_as_uint(f);
    return (u & 0x80000000u) ? ~u : (u | 0x80000000u);
}
__device__ __forceinline__ float fdec(unsigned u) {
    return (u & 0x80000000u) ? __uint_as_float(u & 0x7fffffffu)
                             : __uint_as_float(~u);
}

// ---------------------------------------------------------------------------
// Detect index dtype: if the first entries interpreted as int64 are all valid
// node ids, it's int64; otherwise int32. (int32 data read as int64 produces
// huge values with overwhelming probability.)
// ---------------------------------------------------------------------------
__global__ void detect_kernel(const void* src, int E, int N) {
    if (threadIdx.x == 0 && blockIdx.x == 0) {
        const long long* p = (const long long*)src;
        int n = E < 256 ? E : 256;
        int ok = 1;
        for (int i = 0; i < n; i++) {
            long long v = p[i];
            if (v < 0 || v >= (long long)N) { ok = 0; break; }
        }
        g_idx64 = ok;
    }
}

// ---------------------------------------------------------------------------
// init: zero the neigh-encoding buffer (sentinel = 0u)
// ---------------------------------------------------------------------------
__global__ void init_neigh_kernel(int n_uint4) {
    int i = blockIdx.x * blockDim.x + threadIdx.x;
    if (i < n_uint4) {
        ((uint4*)g_neigh)[i] = make_uint4(0u, 0u, 0u, 0u);
    }
}

// ---------------------------------------------------------------------------
// Classic SGEMM: C[M x 128] = A[M x K] @ W[128 x K]^T + bias
// BM=BN=128, BK=16, 256 threads, 8x8 per thread.
// CONCAT: K=256, k>=128 reads decoded g_neigh (sentinel -> 0).
// WRITE_H: output goes to g_h instead of C.
// ---------------------------------------------------------------------------
template <int K, bool CONCAT, bool WRITE_H>
__global__ __launch_bounds__(256, 2)
void sgemm_kernel(const float* __restrict__ A,
                  const float* __restrict__ W,
                  const float* __restrict__ bias,
                  float* __restrict__ C, int M)
{
    __shared__ float As[16][132];
    __shared__ float Ws[16][132];

    const int tid  = threadIdx.x;
    const int tx   = tid & 15;   // col group
    const int ty   = tid >> 4;   // row group
    const int row0 = blockIdx.x * 128;

    float acc[8][8];
    #pragma unroll
    for (int i = 0; i < 8; i++)
        #pragma unroll
        for (int j = 0; j < 8; j++) acc[i][j] = 0.f;

    for (int k0 = 0; k0 < K; k0 += 16) {
        // ---- load tiles (transposed into smem: [k][m]/[k][n]) ----
        #pragma unroll
        for (int it = 0; it < 2; it++) {
            int f  = tid + it * 256;   // float4 slot 0..511
            int r  = f >> 2;           // 0..127
            int c  = (f & 3) << 2;     // 0,4,8,12
            int gk = k0 + c;

            // A tile (rows may be out of range)
            int gr = row0 + r;
            float4 v = make_float4(0.f, 0.f, 0.f, 0.f);
            if (gr < M) {
                if (!CONCAT || gk < FEAT_D) {
                    v = *(const float4*)(A + (size_t)gr * FEAT_D + gk);
                } else {
                    uint4 u = *(const uint4*)(g_neigh + (size_t)gr * FEAT_D + (gk - FEAT_D));
                    v.x = u.x ? fdec(u.x) : 0.f;
                    v.y = u.y ? fdec(u.y) : 0.f;
                    v.z = u.z ? fdec(u.z) : 0.f;
                    v.w = u.w ? fdec(u.w) : 0.f;
                }
            }
            As[c + 0][r] = v.x; As[c + 1][r] = v.y;
            As[c + 2][r] = v.z; As[c + 3][r] = v.w;

            // W tile (N = 128 rows always valid)
            float4 wv = *(const float4*)(W + (size_t)r * K + gk);
            Ws[c + 0][r] = wv.x; Ws[c + 1][r] = wv.y;
            Ws[c + 2][r] = wv.z; Ws[c + 3][r] = wv.w;
        }
        __syncthreads();

        // ---- compute ----
        #pragma unroll
        for (int k = 0; k < 16; k++) {
            float a[8], w[8];
            #pragma unroll
            for (int i = 0; i < 8; i++) a[i] = As[k][ty * 8 + i];
            #pragma unroll
            for (int j = 0; j < 8; j++) w[j] = Ws[k][tx * 8 + j];
            #pragma unroll
            for (int i = 0; i < 8; i++)
                #pragma unroll
                for (int j = 0; j < 8; j++)
                    acc[i][j] += a[i] * w[j];
        }
        __syncthreads();
    }

    // ---- epilogue ----
    float b[8];
    #pragma unroll
    for (int j = 0; j < 8; j++) b[j] = bias[tx * 8 + j];

    #pragma unroll
    for (int i = 0; i < 8; i++) {
        int gr = row0 + ty * 8 + i;
        if (gr >= M) continue;
        float* dstp = (WRITE_H ? g_h : C) + (size_t)gr * FEAT_D + tx * 8;
        float4 o0 = make_float4(acc[i][0] + b[0], acc[i][1] + b[1],
                                acc[i][2] + b[2], acc[i][3] + b[3]);
        float4 o1 = make_float4(acc[i][4] + b[4], acc[i][5] + b[5],
                                acc[i][6] + b[6], acc[i][7] + b[7]);
        *(float4*)(dstp)     = o0;
        *(float4*)(dstp + 4) = o1;
    }
}

// ---------------------------------------------------------------------------
// Edge kernel: one warp per edge. Gather h[src] (L2-resident), scale by w,
// scatter-max into g_neigh[dst] via order-encoded atomicMax.
// Read-and-filter before the atomic: values grow monotonically, so any cached
// (possibly stale) value is <= current -> skipping when candidate <= cached
// is always safe, and cuts RMW traffic ~4x.
// Index dtype resolved at runtime via g_idx64; indices hard-guarded.
// ---------------------------------------------------------------------------
__global__ void edge_kernel(const float* __restrict__ weight,
                            const void* __restrict__ src,
                            const void* __restrict__ dst,
                            int E, int N)
{
    int warp = (blockIdx.x * blockDim.x + threadIdx.x) >> 5;
    int lane = threadIdx.x & 31;
    if (warp >= E) return;

    int s, d;
    if (g_idx64) {
        s = (int)((const long long*)src)[warp];
        d = (int)((const long long*)dst)[warp];
    } else {
        s = ((const int*)src)[warp];
        d = ((const int*)dst)[warp];
    }
    if ((unsigned)s >= (unsigned)N || (unsigned)d >= (unsigned)N) return;

    float w = weight[warp];

    float4 v = *(const float4*)(g_h + (size_t)s * FEAT_D + lane * 4);
    unsigned e0 = fenc(v.x * w);
    unsigned e1 = fenc(v.y * w);
    unsigned e2 = fenc(v.z * w);
    unsigned e3 = fenc(v.w * w);

    unsigned* outp = g_neigh + (size_t)d * FEAT_D + lane * 4;
    uint4 cur = *(const uint4*)outp;
    if (e0 > cur.x) atomicMax(outp + 0, e0);
    if (e1 > cur.y) atomicMax(outp + 1, e1);
    if (e2 > cur.z) atomicMax(outp + 2, e2);
    if (e3 > cur.w) atomicMax(outp + 3, e3);
}

// ---------------------------------------------------------------------------
extern "C" void kernel_launch(void* const* d_in, const int* in_sizes, int n_in,
                              void* d_out, int out_size)
{
    const float* feat    = (const float*)d_in[0];
    const float* weight  = (const float*)d_in[1];
    const void*  src     = d_in[2];
    const void*  dst     = d_in[3];
    const float* W_pool  = (const float*)d_in[4];
    const float* b_pool  = (const float*)d_in[5];
    const float* W_neigh = (const float*)d_in[6];
    const float* b_neigh = (const float*)d_in[7];
    float*       out     = (float*)d_out;

    const int N = in_sizes[0] / FEAT_D;   // 50000
    const int E = in_sizes[1];            // 640000

    const int gemm_blocks = (N + 127) / 128;

    // 0) resolve index dtype (int32 vs int64)
    detect_kernel<<<1, 1>>>(src, E, N);

    // 1) h = feat @ W_pool^T + b_pool   (written to g_h)
    sgemm_kernel<128, false, true><<<gemm_blocks, 256>>>(feat, W_pool, b_pool, nullptr, N);

    // 2) init neigh sentinel
    {
        int n4 = (N * FEAT_D) / 4;
        init_neigh_kernel<<<(n4 + 255) / 256, 256>>>(n4);
    }

    // 3) scatter-max over edges (1 warp / edge)
    {
        int warps_per_block = 256 / 32;
        int blocks = (E + warps_per_block - 1) / warps_per_block;
        edge_kernel<<<blocks, 256>>>(weight, src, dst, E, N);
    }

    // 4) out = concat(feat, neigh) @ W_neigh^T + b_neigh
    sgemm_kernel<256, true, false><<<gemm_blocks, 256>>>(feat, W_neigh, b_neigh, out, N);
}

// round 5
// speedup vs baseline: 1.3583x; 1.3583x over previous
#include <cuda_runtime.h>

#define FEAT_D 128
#define MAX_NODES 50016
#define MAX_EDGES 650240

// ---- scratch (__device__ globals; no allocation allowed) ----
__device__ float g_h[MAX_NODES * FEAT_D];       // pooled features after GEMM1
__device__ float g_neigh[MAX_NODES * FEAT_D];   // per-node max-pooled neighborhood
__device__ int   g_deg[MAX_NODES];
__device__ int   g_incl[MAX_NODES];             // per-block inclusive scan
__device__ int   g_bsum[256];                   // per-block totals
__device__ int   g_bbase[256];                  // exclusive block bases
__device__ int   g_offs[MAX_NODES + 1];         // CSR row offsets
__device__ int   g_cursor[MAX_NODES];           // scatter cursors
__device__ int2  g_rec[MAX_EDGES];              // (src, weight-bits) per edge, grouped by dst
__device__ int   g_idx64;                       // 1 if src/dst are int64

// ---------------------------------------------------------------------------
__global__ void detect_kernel(const void* src, int E, int N) {
    if (threadIdx.x == 0 && blockIdx.x == 0) {
        const long long* p = (const long long*)src;
        int n = E < 256 ? E : 256;
        int ok = 1;
        for (int i = 0; i < n; i++) {
            long long v = p[i];
            if (v < 0 || v >= (long long)N) { ok = 0; break; }
        }
        g_idx64 = ok;
    }
}

__device__ __forceinline__ int load_idx(const void* p, int i) {
    return g_idx64 ? (int)((const long long*)p)[i] : ((const int*)p)[i];
}

// ---------------------------------------------------------------------------
__global__ void zero_deg_kernel(int n) {
    int i = blockIdx.x * blockDim.x + threadIdx.x;
    if (i < n) g_deg[i] = 0;
}

__global__ void count_kernel(const void* __restrict__ dst, int E, int N) {
    int e = blockIdx.x * blockDim.x + threadIdx.x;
    if (e >= E) return;
    int d = load_idx(dst, e);
    if ((unsigned)d < (unsigned)N) atomicAdd(&g_deg[d], 1);
}

// per-block inclusive scan (block = 512)
__global__ void scan1_kernel(int n) {
    __shared__ int s[512];
    int tid = threadIdx.x;
    int i = blockIdx.x * 512 + tid;
    int v = (i < n) ? g_deg[i] : 0;
    s[tid] = v;
    __syncthreads();
    #pragma unroll
    for (int off = 1; off < 512; off <<= 1) {
        int t = (tid >= off) ? s[tid - off] : 0;
        __syncthreads();
        s[tid] += t;
        __syncthreads();
    }
    if (i < n) g_incl[i] = s[tid];
    if (tid == 511) g_bsum[blockIdx.x] = s[511];
}

// scan the (<=256) block totals -> exclusive bases. single block of 256.
__global__ void scan2_kernel(int nblocks) {
    __shared__ int s[256];
    int tid = threadIdx.x;
    int v = (tid < nblocks) ? g_bsum[tid] : 0;
    s[tid] = v;
    __syncthreads();
    #pragma unroll
    for (int off = 1; off < 256; off <<= 1) {
        int t = (tid >= off) ? s[tid - off] : 0;
        __syncthreads();
        s[tid] += t;
        __syncthreads();
    }
    if (tid < nblocks) g_bbase[tid] = s[tid] - v;   // exclusive
}

__global__ void scan3_kernel(int n, int E) {
    int i = blockIdx.x * 512 + threadIdx.x;
    if (i >= n) return;
    int ex = g_incl[i] - g_deg[i] + g_bbase[blockIdx.x];
    g_offs[i]   = ex;
    g_cursor[i] = ex;
    if (i == n - 1) g_offs[n] = E;
}

__global__ void scatter_kernel(const float* __restrict__ weight,
                               const void* __restrict__ src,
                               const void* __restrict__ dst,
                               int E, int N) {
    int e = blockIdx.x * blockDim.x + threadIdx.x;
    if (e >= E) return;
    int d = load_idx(dst, e);
    int s = load_idx(src, e);
    if ((unsigned)d >= (unsigned)N || (unsigned)s >= (unsigned)N) return;
    int pos = atomicAdd(&g_cursor[d], 1);
    g_rec[pos] = make_int2(s, __float_as_int(weight[e]));
}

// ---------------------------------------------------------------------------
// Node-max: one warp per node; lane owns float4 slot. Unroll x4 for MLP on
// the random L2-resident gathers of g_h. No atomics.
// ---------------------------------------------------------------------------
__global__ void __launch_bounds__(256)
nodemax_kernel(int N) {
    int warp = (blockIdx.x * blockDim.x + threadIdx.x) >> 5;
    int lane = threadIdx.x & 31;
    if (warp >= N) return;

    int beg = g_offs[warp];
    int end = g_offs[warp + 1];

    float* outp = g_neigh + (size_t)warp * FEAT_D + lane * 4;
    if (beg == end) {   // zero-degree -> 0
        *(float4*)outp = make_float4(0.f, 0.f, 0.f, 0.f);
        return;
    }

    const float NEG = -3.402823466e+38f;
    float4 m = make_float4(NEG, NEG, NEG, NEG);

    int e = beg;
    for (; e + 4 <= end; e += 4) {
        int2 r0 = g_rec[e + 0];
        int2 r1 = g_rec[e + 1];
        int2 r2 = g_rec[e + 2];
        int2 r3 = g_rec[e + 3];
        float4 v0 = *(const float4*)(g_h + (size_t)r0.x * FEAT_D + lane * 4);
        float4 v1 = *(const float4*)(g_h + (size_t)r1.x * FEAT_D + lane * 4);
        float4 v2 = *(const float4*)(g_h + (size_t)r2.x * FEAT_D + lane * 4);
        float4 v3 = *(const float4*)(g_h + (size_t)r3.x * FEAT_D + lane * 4);
        float w0 = __int_as_float(r0.y), w1 = __int_as_float(r1.y);
        float w2 = __int_as_float(r2.y), w3 = __int_as_float(r3.y);
        m.x = fmaxf(m.x, v0.x * w0); m.y = fmaxf(m.y, v0.y * w0);
        m.z = fmaxf(m.z, v0.z * w0); m.w = fmaxf(m.w, v0.w * w0);
        m.x = fmaxf(m.x, v1.x * w1); m.y = fmaxf(m.y, v1.y * w1);
        m.z = fmaxf(m.z, v1.z * w1); m.w = fmaxf(m.w, v1.w * w1);
        m.x = fmaxf(m.x, v2.x * w2); m.y = fmaxf(m.y, v2.y * w2);
        m.z = fmaxf(m.z, v2.z * w2); m.w = fmaxf(m.w, v2.w * w2);
        m.x = fmaxf(m.x, v3.x * w3); m.y = fmaxf(m.y, v3.y * w3);
        m.z = fmaxf(m.z, v3.z * w3); m.w = fmaxf(m.w, v3.w * w3);
    }
    for (; e < end; e++) {
        int2 r = g_rec[e];
        float w = __int_as_float(r.y);
        float4 v = *(const float4*)(g_h + (size_t)r.x * FEAT_D + lane * 4);
        m.x = fmaxf(m.x, v.x * w); m.y = fmaxf(m.y, v.y * w);
        m.z = fmaxf(m.z, v.z * w); m.w = fmaxf(m.w, v.w * w);
    }
    *(float4*)outp = m;
}

// ---------------------------------------------------------------------------
// Classic SGEMM: C[M x 128] = A[M x K] @ W[128 x K]^T + bias
// BM=BN=128, BK=16, 256 threads, 8x8 per thread.
// CONCAT: K=256, k>=128 reads g_neigh.
// WRITE_H: output goes to g_h instead of C.
// ---------------------------------------------------------------------------
template <int K, bool CONCAT, bool WRITE_H>
__global__ __launch_bounds__(256, 2)
void sgemm_kernel(const float* __restrict__ A,
                  const float* __restrict__ W,
                  const float* __restrict__ bias,
                  float* __restrict__ C, int M)
{
    __shared__ float As[16][132];
    __shared__ float Ws[16][132];

    const int tid  = threadIdx.x;
    const int tx   = tid & 15;
    const int ty   = tid >> 4;
    const int row0 = blockIdx.x * 128;

    float acc[8][8];
    #pragma unroll
    for (int i = 0; i < 8; i++)
        #pragma unroll
        for (int j = 0; j < 8; j++) acc[i][j] = 0.f;

    for (int k0 = 0; k0 < K; k0 += 16) {
        #pragma unroll
        for (int it = 0; it < 2; it++) {
            int f  = tid + it * 256;
            int r  = f >> 2;
            int c  = (f & 3) << 2;
            int gk = k0 + c;

            int gr = row0 + r;
            float4 v = make_float4(0.f, 0.f, 0.f, 0.f);
            if (gr < M) {
                if (!CONCAT || gk < FEAT_D) {
                    v = *(const float4*)(A + (size_t)gr * FEAT_D + gk);
                } else {
                    v = *(const float4*)(g_neigh + (size_t)gr * FEAT_D + (gk - FEAT_D));
                }
            }
            As[c + 0][r] = v.x; As[c + 1][r] = v.y;
            As[c + 2][r] = v.z; As[c + 3][r] = v.w;

            float4 wv = *(const float4*)(W + (size_t)r * K + gk);
            Ws[c + 0][r] = wv.x; Ws[c + 1][r] = wv.y;
            Ws[c + 2][r] = wv.z; Ws[c + 3][r] = wv.w;
        }
        __syncthreads();

        #pragma unroll
        for (int k = 0; k < 16; k++) {
            float a[8], w[8];
            #pragma unroll
            for (int i = 0; i < 8; i++) a[i] = As[k][ty * 8 + i];
            #pragma unroll
            for (int j = 0; j < 8; j++) w[j] = Ws[k][tx * 8 + j];
            #pragma unroll
            for (int i = 0; i < 8; i++)
                #pragma unroll
                for (int j = 0; j < 8; j++)
                    acc[i][j] += a[i] * w[j];
        }
        __syncthreads();
    }

    float b[8];
    #pragma unroll
    for (int j = 0; j < 8; j++) b[j] = bias[tx * 8 + j];

    #pragma unroll
    for (int i = 0; i < 8; i++) {
        int gr = row0 + ty * 8 + i;
        if (gr >= M) continue;
        float* dstp = (WRITE_H ? g_h : C) + (size_t)gr * FEAT_D + tx * 8;
        *(float4*)(dstp)     = make_float4(acc[i][0] + b[0], acc[i][1] + b[1],
                                           acc[i][2] + b[2], acc[i][3] + b[3]);
        *(float4*)(dstp + 4) = make_float4(acc[i][4] + b[4], acc[i][5] + b[5],
                                           acc[i][6] + b[6], acc[i][7] + b[7]);
    }
}

// ---------------------------------------------------------------------------
extern "C" void kernel_launch(void* const* d_in, const int* in_sizes, int n_in,
                              void* d_out, int out_size)
{
    const float* feat    = (const float*)d_in[0];
    const float* weight  = (const float*)d_in[1];
    const void*  src     = d_in[2];
    const void*  dst     = d_in[3];
    const float* W_pool  = (const float*)d_in[4];
    const float* b_pool  = (const float*)d_in[5];
    const float* W_neigh = (const float*)d_in[6];
    const float* b_neigh = (const float*)d_in[7];
    float*       out     = (float*)d_out;

    const int N = in_sizes[0] / FEAT_D;   // 50000
    const int E = in_sizes[1];            // 640000

    const int gemm_blocks  = (N + 127) / 128;
    const int scan_blocks  = (N + 511) / 512;

    // 0) resolve index dtype
    detect_kernel<<<1, 1>>>(src, E, N);

    // 1) h = feat @ W_pool^T + b_pool
    sgemm_kernel<128, false, true><<<gemm_blocks, 256>>>(feat, W_pool, b_pool, nullptr, N);

    // 2) CSR build: degrees -> scan -> scatter
    zero_deg_kernel<<<(N + 255) / 256, 256>>>(N);
    count_kernel<<<(E + 255) / 256, 256>>>(dst, E, N);
    scan1_kernel<<<scan_blocks, 512>>>(N);
    scan2_kernel<<<1, 256>>>(scan_blocks);
    scan3_kernel<<<scan_blocks, 512>>>(N, E);
    scatter_kernel<<<(E + 255) / 256, 256>>>(weight, src, dst, E, N);

    // 3) per-node register max (no atomics)
    nodemax_kernel<<<(N * 32 + 255) / 256, 256>>>(N);

    // 4) out = concat(feat, neigh) @ W_neigh^T + b_neigh
    sgemm_kernel<256, true, false><<<gemm_blocks, 256>>>(feat, W_neigh, b_neigh, out, N);
}